// round 9
// baseline (speedup 1.0000x reference)
#include <cuda_runtime.h>
#include <math.h>

#define NN 100000
#define NE 3200000
#define SLOPE 0.01f

// ---------------- scratch (device globals; no allocation allowed) ----------
__device__ __align__(16) int   g_cnt   [NN];
__device__ __align__(16) int   g_rowptr[NN + 1];
__device__ __align__(16) int   g_next  [NN];
__device__ __align__(16) int   g_bsum  [32];
__device__ __align__(16) int   g_csr   [NE];
__device__ __align__(16) float g_dinv  [NN];
__device__ __align__(16) float g_h     [NN*16];   // holds xw1 after gather0
__device__ __align__(16) float g_xw    [NN*16];   // holds xw0 after k_pre
__device__ float g_W[2*256];
__device__ int   g_is64;

__device__ __forceinline__ float lrelu(float v){ return v > 0.f ? v : SLOPE*v; }
__device__ __forceinline__ int   clampi(int v){ return v < 0 ? 0 : (v >= NN ? NN-1 : v); }

// packed fp32x2 helpers (Blackwell)
__device__ __forceinline__ unsigned long long pk2(float a, float b){
    unsigned long long r;
    asm("mov.b64 %0, {%1, %2};" : "=l"(r) : "f"(a), "f"(b));
    return r;
}
__device__ __forceinline__ unsigned long long fma2(unsigned long long a,
                                                   unsigned long long b,
                                                   unsigned long long c){
    unsigned long long d;
    asm("fma.rn.f32x2 %0, %1, %2, %3;" : "=l"(d) : "l"(a), "l"(b), "l"(c));
    return d;
}
__device__ __forceinline__ float2 upk2(unsigned long long v){
    float2 r;
    asm("mov.b64 {%0, %1}, %2;" : "=f"(r.x), "=f"(r.y) : "l"(v));
    return r;
}

// ---------------- fused init: block0=dtype detect, block1=hyper, rest=cnt0 ----
__global__ void __launch_bounds__(512)
k_init(const int* __restrict__ ei32,
       const float* __restrict__ bih, const float* __restrict__ bhh,
       const float* __restrict__ wtW, const float* __restrict__ wtb){
    int b = blockIdx.x;
    if (b == 0){
        __shared__ int any;
        if (threadIdx.x == 0) any = 0;
        __syncthreads();
        int v = 0;
#pragma unroll
        for (int q = 0; q < 6; q++){
            int e = threadIdx.x + 512*q;
            v |= ei32[2*e + 1];
        }
        if (v) atomicOr(&any, 1);
        __syncthreads();
        if (threadIdx.x == 0) g_is64 = (any == 0) ? 1 : 0;
    } else if (b == 1){
        int t = threadIdx.x;
        int l = t >> 8, j = t & 255;
        float mem[16];
#pragma unroll
        for (int m = 0; m < 16; m++){
            float r = 1.f/(1.f + expf(-(bih[l*48 + m]      + bhh[l*48 + m])));
            float z = 1.f/(1.f + expf(-(bih[l*48 + 16 + m] + bhh[l*48 + 16 + m])));
            float n = tanhf(bih[l*48 + 32 + m] + r*bhh[l*48 + 32 + m]);
            mem[m] = (1.f - z) * n;
        }
        float acc = wtb[l*256 + j];
#pragma unroll
        for (int m = 0; m < 16; m++) acc += wtW[(l*256 + j)*16 + m] * mem[m];
        g_W[l*256 + j] = acc;
    } else {
        int i = (b - 2)*512 + threadIdx.x;
        if (i < NN) g_cnt[i] = 0;
    }
}

// ---------------- degree count (dst row only) ----------------------------------
__global__ void k_edges(const int* __restrict__ ei32){
    int p = blockIdx.x*blockDim.x + threadIdx.x;
    if (p >= NE/2) return;
    int d0, d1;
    if (g_is64){
        const longlong2* v = (const longlong2*)ei32;
        longlong2 dv = v[(NE >> 1) + p];
        d0 = (int)dv.x; d1 = (int)dv.y;
    } else {
        const int2* v = (const int2*)ei32;
        int2 dv = v[(NE >> 1) + p];
        d0 = dv.x; d1 = dv.y;
    }
    atomicAdd(&g_cnt[clampi(d0)], 1);
    atomicAdd(&g_cnt[clampi(d1)], 1);
}

// ---------------- exclusive scan over g_cnt -> g_rowptr (+ dinv fused) -----------
__global__ void k_scan1(){
    __shared__ int ts[512];
    int b = blockIdx.x, t = threadIdx.x;
    int base = b*4096 + t*8;
    int v[8]; int s = 0;
#pragma unroll
    for (int k = 0; k < 8; k++){
        v[k] = (base + k < NN) ? g_cnt[base + k] : 0;
        s += v[k];
        if (base + k < NN) g_dinv[base + k] = rsqrtf((float)v[k] + 1.0f);
    }
    ts[t] = s; __syncthreads();
#pragma unroll
    for (int off = 1; off < 512; off <<= 1){
        int y = (t >= off) ? ts[t - off] : 0;
        __syncthreads();
        ts[t] += y;
        __syncthreads();
    }
    if (t == 511) g_bsum[b] = ts[511];
    int run = ts[t] - s;
#pragma unroll
    for (int k = 0; k < 8; k++){
        if (base + k < NN) g_rowptr[base + k] = run;
        run += v[k];
    }
}
// scan3 with inline scan2 (serial 25-prefix in smem)
__global__ void k_scan3(){
    __shared__ int bs[32];
    if (threadIdx.x == 0){
        int run = 0;
        for (int j = 0; j < 25; j++){ bs[j] = run; run += g_bsum[j]; }
    }
    __syncthreads();
    int i = blockIdx.x*blockDim.x + threadIdx.x;
    if (i < NN){
        int r = g_rowptr[i] + bs[i >> 12];
        g_rowptr[i] = r;
        g_next[i]   = r;
    }
    if (i == 0) g_rowptr[NN] = NE;
}

// ---------------- CSR fill (re-decode edge_index) --------------------------------
__global__ void k_fill(const int* __restrict__ ei32){
    int e = blockIdx.x*blockDim.x + threadIdx.x;
    if (e >= NE) return;
    int s, d;
    if (g_is64){
        s = ei32[2*(size_t)e];
        d = ei32[2*((size_t)NE + e)];
    } else {
        s = ei32[e];
        d = ei32[NE + e];
    }
    s = clampi(s); d = clampi(d);
    int pos = atomicAdd(&g_next[d], 1);
    if (pos >= 0 && pos < NE) g_csr[pos] = s;
}

// ---------------- fused preprocess MLP + xw0: 128 -> 256 -> 16 -> (h@W0.T)*dinv ---
// smem layout (floats):
#define P_W1 0         // 32768: blocked w1v[j*256+r] = W1[r][4j..4j+3]
#define P_W2 32768     // 4352 = 256*17 padded transpose
#define P_B2 37120     // 16
#define P_W0 37136     // 256 transposed: W0t[i*16+o] = W0[o][i]
#define P_DV 37392     // 32 dinv for batch
#define P_X  37424     // 4096: 16 pairs x 128 k x float2   (reused as HS in epilogue)
#define P_H1 41520     // 8192: 16 pairs x 256 o x float2
#define P_R  49712     // 8192: 16 pairs x 16 part x 16 o x float2
#define PRE_SMEM_FLOATS 57904
#define PRE_SMEM_BYTES  (PRE_SMEM_FLOATS*4)   // 231616 <= 232448

__global__ void __launch_bounds__(512, 1)
k_pre(const float* __restrict__ x,
      const float* __restrict__ p1W, const float* __restrict__ p1b,
      const float* __restrict__ p2W, const float* __restrict__ p2b){
    extern __shared__ float sm[];
    int t = threadIdx.x;

    // stage weights once
    {
        float4* w1v = (float4*)(sm + P_W1);
        const float4* p1W4 = (const float4*)p1W;
        for (int i = t; i < 8192; i += 512){
            int j = i >> 8, r = i & 255;
            w1v[i] = p1W4[r*32 + j];
        }
        for (int i = t; i < 4096; i += 512){
            int k = i >> 4, o = i & 15;
            sm[P_W2 + k*17 + o] = p2W[o*256 + k];
        }
        if (t < 16) sm[P_B2 + t] = p2b[t];
        if (t < 256) sm[P_W0 + t] = g_W[(t & 15)*16 + (t >> 4)];   // transposed
    }
    __syncthreads();

    const float4*              wv  = (const float4*)(sm + P_W1);
    const ulonglong2*          xq  = (const ulonglong2*)(sm + P_X);
    float2*                    sxp = (float2*)(sm + P_X);
    float2*                    hbp = (float2*)(sm + P_H1);
    const unsigned long long*  hbu = (const unsigned long long*)(sm + P_H1);
    unsigned long long*        sru = (unsigned long long*)(sm + P_R);
    const float2*              srp = (const float2*)(sm + P_R);
    float2*                    HSw = (float2*)(sm + P_X);
    const unsigned long long*  HSu = (const unsigned long long*)(sm + P_X);

    int oo = t & 127;      // output group: columns oo and oo+128
    int pg = t >> 7;       // pair group 0..3 : pairs 4pg..4pg+3
    float b0 = p1b[oo], b1 = p1b[128 + oo];   // layer-1 biases in regs

    // NN % 32 == 0
    for (int base = blockIdx.x*32; base < NN; base += gridDim.x*32){
        // stage 32 nodes as 16 (even,odd) pairs + dinv
#pragma unroll
        for (int r = 0; r < 4; r++){
            int e = t + 512*r;
            int p = e >> 7, k = e & 127;
            sxp[p*128 + k] = make_float2(x[(size_t)(base + 2*p    )*128 + k],
                                         x[(size_t)(base + 2*p + 1)*128 + k]);
        }
        if (t < 32) sm[P_DV + t] = g_dinv[base + t];
        __syncthreads();

        // layer 1: 2 outputs x 4 pairs per thread, packed f32x2 FMA
        unsigned long long a00, a01, a02, a03, a10, a11, a12, a13;
        a00 = a01 = a02 = a03 = pk2(b0, b0);
        a10 = a11 = a12 = a13 = pk2(b1, b1);
        int pb = pg*4;
#pragma unroll 2
        for (int j = 0; j < 32; j++){
            float4 wA = wv[j*256 + oo];
            float4 wB = wv[j*256 + 128 + oo];
            ulonglong2 x0a = xq[(pb+0)*64 + 2*j], x0b = xq[(pb+0)*64 + 2*j + 1];
            ulonglong2 x1a = xq[(pb+1)*64 + 2*j], x1b = xq[(pb+1)*64 + 2*j + 1];
            ulonglong2 x2a = xq[(pb+2)*64 + 2*j], x2b = xq[(pb+2)*64 + 2*j + 1];
            ulonglong2 x3a = xq[(pb+3)*64 + 2*j], x3b = xq[(pb+3)*64 + 2*j + 1];
            unsigned long long wA0 = pk2(wA.x, wA.x), wA1 = pk2(wA.y, wA.y);
            unsigned long long wA2 = pk2(wA.z, wA.z), wA3 = pk2(wA.w, wA.w);
            a00 = fma2(wA0, x0a.x, a00); a00 = fma2(wA1, x0a.y, a00);
            a00 = fma2(wA2, x0b.x, a00); a00 = fma2(wA3, x0b.y, a00);
            a01 = fma2(wA0, x1a.x, a01); a01 = fma2(wA1, x1a.y, a01);
            a01 = fma2(wA2, x1b.x, a01); a01 = fma2(wA3, x1b.y, a01);
            a02 = fma2(wA0, x2a.x, a02); a02 = fma2(wA1, x2a.y, a02);
            a02 = fma2(wA2, x2b.x, a02); a02 = fma2(wA3, x2b.y, a02);
            a03 = fma2(wA0, x3a.x, a03); a03 = fma2(wA1, x3a.y, a03);
            a03 = fma2(wA2, x3b.x, a03); a03 = fma2(wA3, x3b.y, a03);
            unsigned long long wB0 = pk2(wB.x, wB.x), wB1 = pk2(wB.y, wB.y);
            unsigned long long wB2 = pk2(wB.z, wB.z), wB3 = pk2(wB.w, wB.w);
            a10 = fma2(wB0, x0a.x, a10); a10 = fma2(wB1, x0a.y, a10);
            a10 = fma2(wB2, x0b.x, a10); a10 = fma2(wB3, x0b.y, a10);
            a11 = fma2(wB0, x1a.x, a11); a11 = fma2(wB1, x1a.y, a11);
            a11 = fma2(wB2, x1b.x, a11); a11 = fma2(wB3, x1b.y, a11);
            a12 = fma2(wB0, x2a.x, a12); a12 = fma2(wB1, x2a.y, a12);
            a12 = fma2(wB2, x2b.x, a12); a12 = fma2(wB3, x2b.y, a12);
            a13 = fma2(wB0, x3a.x, a13); a13 = fma2(wB1, x3a.y, a13);
            a13 = fma2(wB2, x3b.x, a13); a13 = fma2(wB3, x3b.y, a13);
        }
        {
            float2 y;
            y = upk2(a00); hbp[(pb+0)*256 + oo]       = make_float2(lrelu(y.x), lrelu(y.y));
            y = upk2(a01); hbp[(pb+1)*256 + oo]       = make_float2(lrelu(y.x), lrelu(y.y));
            y = upk2(a02); hbp[(pb+2)*256 + oo]       = make_float2(lrelu(y.x), lrelu(y.y));
            y = upk2(a03); hbp[(pb+3)*256 + oo]       = make_float2(lrelu(y.x), lrelu(y.y));
            y = upk2(a10); hbp[(pb+0)*256 + 128 + oo] = make_float2(lrelu(y.x), lrelu(y.y));
            y = upk2(a11); hbp[(pb+1)*256 + 128 + oo] = make_float2(lrelu(y.x), lrelu(y.y));
            y = upk2(a12); hbp[(pb+2)*256 + 128 + oo] = make_float2(lrelu(y.x), lrelu(y.y));
            y = upk2(a13); hbp[(pb+3)*256 + 128 + oo] = make_float2(lrelu(y.x), lrelu(y.y));
        }
        __syncthreads();

        // layer 2 partials: thread (o = t&15, part = (t>>4)&15, h = t>>8)
        {
            int o = t & 15, part = (t >> 4) & 15, h = t >> 8;
            unsigned long long acc[8];
#pragma unroll
            for (int q = 0; q < 8; q++) acc[q] = 0ULL;
#pragma unroll
            for (int kk = 0; kk < 16; kk++){
                int k = part*16 + kk;
                float w2s = sm[P_W2 + k*17 + o];
                unsigned long long w2 = pk2(w2s, w2s);
#pragma unroll
                for (int q = 0; q < 8; q++)
                    acc[q] = fma2(w2, hbu[(h*8 + q)*256 + k], acc[q]);
            }
#pragma unroll
            for (int q = 0; q < 8; q++)
                sru[(h*8 + q)*256 + part*16 + o] = acc[q];
        }
        __syncthreads();

        // final h (pair-packed) into HS scratch (reuses x region)
        if (t < 256){
            int pair = t >> 4, o = t & 15;
            float sx = 0.f, sy = 0.f;
#pragma unroll
            for (int p = 0; p < 16; p++){
                float2 v = srp[pair*256 + p*16 + o];
                sx += v.x; sy += v.y;
            }
            float bb2 = sm[P_B2 + o];
            HSw[t] = make_float2(lrelu(sx + bb2), lrelu(sy + bb2));
        }
        __syncthreads();

        // fused xw0 = (h @ W0^T) * dinv  -> g_xw
        if (t < 256){
            int pair = t >> 4, o = t & 15;
            unsigned long long acc = 0ULL;
#pragma unroll
            for (int i = 0; i < 16; i++){
                float w = sm[P_W0 + i*16 + o];
                acc = fma2(pk2(w, w), HSu[pair*16 + i], acc);
            }
            float2 v = upk2(acc);
            g_xw[(size_t)(base + 2*pair    )*16 + o] = v.x * sm[P_DV + 2*pair];
            g_xw[(size_t)(base + 2*pair + 1)*16 + o] = v.y * sm[P_DV + 2*pair + 1];
        }
        __syncthreads();
    }
}

// ---------------- gather layer 0 + fused xw1 ---------------------------------------
// reads xw0 (g_xw), writes xw1 (g_h)
__global__ void __launch_bounds__(256)
k_gather0(const float* __restrict__ gcnb){
    __shared__ float Ws[256];   // W1 transposed: Ws[i*16+o] = W1[o][i]
    Ws[threadIdx.x] = g_W[256 + (threadIdx.x & 15)*16 + (threadIdx.x >> 4)];
    __syncthreads();

    int warp = (blockIdx.x*blockDim.x + threadIdx.x) >> 5;
    int lane = threadIdx.x & 31;
    if (warp >= NN) return;
    int node = warp;
    int slot = lane >> 2;
    int cg   = lane & 3;
    int beg = g_rowptr[node], end = g_rowptr[node + 1];
    const float4* xw4 = (const float4*)g_xw;

    float4 acc;
    if (slot == 0) acc = xw4[(size_t)node*4 + cg];
    else           acc = make_float4(0.f, 0.f, 0.f, 0.f);

    for (int j = beg + slot; j < end; j += 8){
        int s = g_csr[j];
        float4 v = xw4[(size_t)s*4 + cg];
        acc.x += v.x; acc.y += v.y; acc.z += v.z; acc.w += v.w;
    }
#pragma unroll
    for (int off = 4; off < 32; off <<= 1){
        acc.x += __shfl_xor_sync(0xffffffff, acc.x, off);
        acc.y += __shfl_xor_sync(0xffffffff, acc.y, off);
        acc.z += __shfl_xor_sync(0xffffffff, acc.z, off);
        acc.w += __shfl_xor_sync(0xffffffff, acc.w, off);
    }
    // every lane now has the totals for its cg
    float di = g_dinv[node];
    const float* bp = gcnb + cg*4;   // l = 0
    float4 r;
    r.x = lrelu(di*acc.x + bp[0]);
    r.y = lrelu(di*acc.y + bp[1]);
    r.z = lrelu(di*acc.z + bp[2]);
    r.w = lrelu(di*acc.w + bp[3]);

    // assemble full h via quad shuffles, then 16 lanes compute xw1
    float hv[16];
    int qb = lane & ~3;
#pragma unroll
    for (int c = 0; c < 4; c++){
        int src = qb + c;
        hv[c*4+0] = __shfl_sync(0xffffffff, r.x, src);
        hv[c*4+1] = __shfl_sync(0xffffffff, r.y, src);
        hv[c*4+2] = __shfl_sync(0xffffffff, r.z, src);
        hv[c*4+3] = __shfl_sync(0xffffffff, r.w, src);
    }
    if (lane < 16){
        float a = 0.f;
#pragma unroll
        for (int i = 0; i < 16; i++) a += hv[i]*Ws[i*16 + lane];
        g_h[(size_t)node*16 + lane] = a * di;
    }
}

// ---------------- gather layer 1 + fused post heads ---------------------------------
// reads xw1 (g_h), writes out
__global__ void __launch_bounds__(256)
k_gather2(const float* __restrict__ gcnb,
          const float* __restrict__ po1W, const float* __restrict__ po1b,
          const float* __restrict__ poaW, const float* __restrict__ poab,
          float* __restrict__ out, int out_size){
    int warp = (blockIdx.x*blockDim.x + threadIdx.x) >> 5;
    int lane = threadIdx.x & 31;
    if (warp >= NN) return;
    int node = warp;
    int slot = lane >> 2;
    int cg   = lane & 3;
    int beg = g_rowptr[node], end = g_rowptr[node + 1];
    const float4* xw4 = (const float4*)g_h;

    float4 acc;
    if (slot == 0) acc = xw4[(size_t)node*4 + cg];
    else           acc = make_float4(0.f, 0.f, 0.f, 0.f);

    for (int j = beg + slot; j < end; j += 8){
        int s = g_csr[j];
        float4 v = xw4[(size_t)s*4 + cg];
        acc.x += v.x; acc.y += v.y; acc.z += v.z; acc.w += v.w;
    }
#pragma unroll
    for (int off = 4; off < 32; off <<= 1){
        acc.x += __shfl_xor_sync(0xffffffff, acc.x, off);
        acc.y += __shfl_xor_sync(0xffffffff, acc.y, off);
        acc.z += __shfl_xor_sync(0xffffffff, acc.z, off);
        acc.w += __shfl_xor_sync(0xffffffff, acc.w, off);
    }
    if (lane < 4){
        float di = g_dinv[node];
        const float* bp = gcnb + 16 + cg*4;   // l = 1
        float4 r;
        r.x = lrelu(di*acc.x + bp[0]);
        r.y = lrelu(di*acc.y + bp[1]);
        r.z = lrelu(di*acc.z + bp[2]);
        r.w = lrelu(di*acc.w + bp[3]);
        if (out_size >= 18*NN)
            ((float4*)(out + 2*NN))[(size_t)node*4 + cg] = r;
        int c0 = cg*4;
        float sp = r.x*(po1W[c0+0] + po1W[16+c0+0])
                 + r.y*(po1W[c0+1] + po1W[16+c0+1])
                 + r.z*(po1W[c0+2] + po1W[16+c0+2])
                 + r.w*(po1W[c0+3] + po1W[16+c0+3]);
        float ap = r.x*poaW[c0+0] + r.y*poaW[c0+1]
                 + r.z*poaW[c0+2] + r.w*poaW[c0+3];
        unsigned qm = 0xFu << ((lane >> 2) << 2);
        sp += __shfl_xor_sync(qm, sp, 1); sp += __shfl_xor_sync(qm, sp, 2);
        ap += __shfl_xor_sync(qm, ap, 1); ap += __shfl_xor_sync(qm, ap, 2);
        if (cg == 0){
            out[node] = sp + po1b[0] + po1b[1];
            if (out_size >= 2*NN) out[NN + node] = ap + poab[0];
        }
    }
}

// ---------------- launch --------------------------------------------------------------
extern "C" void kernel_launch(void* const* d_in, const int* in_sizes, int n_in,
                              void* d_out, int out_size){
    const float* x    = (const float*)d_in[0];
    const int*   ei32 = (const int*)d_in[1];
    const float* p1W  = (const float*)d_in[2];
    const float* p1b  = (const float*)d_in[3];
    const float* p2W  = (const float*)d_in[4];
    const float* p2b  = (const float*)d_in[5];
    const float* bih  = (const float*)d_in[6];
    const float* bhh  = (const float*)d_in[7];
    const float* wtW  = (const float*)d_in[8];
    const float* wtb  = (const float*)d_in[9];
    const float* gcnb = (const float*)d_in[10];
    const float* po1W = (const float*)d_in[11];
    const float* po1b = (const float*)d_in[12];
    const float* poaW = (const float*)d_in[13];
    const float* poab = (const float*)d_in[14];
    float* out = (float*)d_out;

    cudaFuncSetAttribute(k_pre, cudaFuncAttributeMaxDynamicSharedMemorySize,
                         PRE_SMEM_BYTES);

    const int NB_N = (NN + 255)/256;
    const int NB_E = (NE + 255)/256;
    const int NB_E2 = (NE/2 + 255)/256;
    const int NB_SCAN = (NN + 4095)/4096;   // 25
    const int NB_G = (NN*32 + 255)/256;     // warp per node
    const int NB_I = 2 + (NN + 511)/512;

    // launch index:        0       1        2        3 (profiled slot)
    k_init   <<<NB_I, 512>>>(ei32, bih, bhh, wtW, wtb);
    k_edges  <<<NB_E2, 256>>>(ei32);
    k_scan1  <<<NB_SCAN, 512>>>();
    k_pre    <<<148, 512, PRE_SMEM_BYTES>>>(x, p1W, p1b, p2W, p2b);
    k_scan3  <<<NB_N, 256>>>();
    k_fill   <<<NB_E, 256>>>(ei32);
    k_gather0<<<NB_G, 256>>>(gcnb);
    k_gather2<<<NB_G, 256>>>(gcnb, po1W, po1b, poaW, poab, out, out_size);
}

// round 10
// speedup vs baseline: 1.0601x; 1.0601x over previous
#include <cuda_runtime.h>
#include <math.h>

#define NN 100000
#define NE 3200000
#define SLOPE 0.01f

// ---------------- scratch (device globals; no allocation allowed) ----------
__device__ __align__(16) int   g_cnt   [NN];
__device__ __align__(16) int   g_rowptr[NN + 1];
__device__ __align__(16) int   g_next  [NN];
__device__ __align__(16) int   g_bsum  [32];
__device__ __align__(16) int   g_csr   [NE];
__device__ __align__(16) float g_dinv  [NN];
__device__ __align__(16) float g_h     [NN*16];   // xw1 after gather0
__device__ __align__(16) float g_xw    [NN*16];   // xw0 after k_pre
__device__ float g_W[2*256];
__device__ int   g_is64;

__device__ __forceinline__ float lrelu(float v){ return v > 0.f ? v : SLOPE*v; }
__device__ __forceinline__ int   clampi(int v){ return v < 0 ? 0 : (v >= NN ? NN-1 : v); }

// packed fp32x2 helpers (Blackwell)
__device__ __forceinline__ unsigned long long pk2(float a, float b){
    unsigned long long r;
    asm("mov.b64 %0, {%1, %2};" : "=l"(r) : "f"(a), "f"(b));
    return r;
}
__device__ __forceinline__ unsigned long long fma2(unsigned long long a,
                                                   unsigned long long b,
                                                   unsigned long long c){
    unsigned long long d;
    asm("fma.rn.f32x2 %0, %1, %2, %3;" : "=l"(d) : "l"(a), "l"(b), "l"(c));
    return d;
}
__device__ __forceinline__ float2 upk2(unsigned long long v){
    float2 r;
    asm("mov.b64 {%0, %1}, %2;" : "=f"(r.x), "=f"(r.y) : "l"(v));
    return r;
}

// ---------------- fused init: block0=dtype detect, block1=hyper, rest=cnt0 ----
__global__ void __launch_bounds__(512)
k_init(const int* __restrict__ ei32,
       const float* __restrict__ bih, const float* __restrict__ bhh,
       const float* __restrict__ wtW, const float* __restrict__ wtb){
    int b = blockIdx.x;
    if (b == 0){
        __shared__ int any;
        if (threadIdx.x == 0) any = 0;
        __syncthreads();
        int v = 0;
#pragma unroll
        for (int q = 0; q < 6; q++){
            int e = threadIdx.x + 512*q;
            v |= ei32[2*e + 1];
        }
        if (v) atomicOr(&any, 1);
        __syncthreads();
        if (threadIdx.x == 0) g_is64 = (any == 0) ? 1 : 0;
    } else if (b == 1){
        int t = threadIdx.x;
        int l = t >> 8, j = t & 255;
        float mem[16];
#pragma unroll
        for (int m = 0; m < 16; m++){
            float r = 1.f/(1.f + expf(-(bih[l*48 + m]      + bhh[l*48 + m])));
            float z = 1.f/(1.f + expf(-(bih[l*48 + 16 + m] + bhh[l*48 + 16 + m])));
            float n = tanhf(bih[l*48 + 32 + m] + r*bhh[l*48 + 32 + m]);
            mem[m] = (1.f - z) * n;
        }
        float acc = wtb[l*256 + j];
#pragma unroll
        for (int m = 0; m < 16; m++) acc += wtW[(l*256 + j)*16 + m] * mem[m];
        g_W[l*256 + j] = acc;
    } else {
        int i = (b - 2)*512 + threadIdx.x;
        if (i < NN) g_cnt[i] = 0;
    }
}

// ---------------- degree count (dst row only) ----------------------------------
__global__ void k_edges(const int* __restrict__ ei32){
    int p = blockIdx.x*blockDim.x + threadIdx.x;
    if (p >= NE/2) return;
    int d0, d1;
    if (g_is64){
        const longlong2* v = (const longlong2*)ei32;
        longlong2 dv = v[(NE >> 1) + p];
        d0 = (int)dv.x; d1 = (int)dv.y;
    } else {
        const int2* v = (const int2*)ei32;
        int2 dv = v[(NE >> 1) + p];
        d0 = dv.x; d1 = dv.y;
    }
    atomicAdd(&g_cnt[clampi(d0)], 1);
    atomicAdd(&g_cnt[clampi(d1)], 1);
}

// ---------------- exclusive scan over g_cnt -> g_rowptr (+ dinv fused) -----------
__global__ void k_scan1(){
    __shared__ int ts[512];
    int b = blockIdx.x, t = threadIdx.x;
    int base = b*4096 + t*8;
    int v[8]; int s = 0;
#pragma unroll
    for (int k = 0; k < 8; k++){
        v[k] = (base + k < NN) ? g_cnt[base + k] : 0;
        s += v[k];
        if (base + k < NN) g_dinv[base + k] = rsqrtf((float)v[k] + 1.0f);
    }
    ts[t] = s; __syncthreads();
#pragma unroll
    for (int off = 1; off < 512; off <<= 1){
        int y = (t >= off) ? ts[t - off] : 0;
        __syncthreads();
        ts[t] += y;
        __syncthreads();
    }
    if (t == 511) g_bsum[b] = ts[511];
    int run = ts[t] - s;
#pragma unroll
    for (int k = 0; k < 8; k++){
        if (base + k < NN) g_rowptr[base + k] = run;
        run += v[k];
    }
}
// scan3 with inline scan2
__global__ void k_scan3(){
    __shared__ int bs[32];
    if (threadIdx.x == 0){
        int run = 0;
        for (int j = 0; j < 25; j++){ bs[j] = run; run += g_bsum[j]; }
    }
    __syncthreads();
    int i = blockIdx.x*blockDim.x + threadIdx.x;
    if (i < NN){
        int r = g_rowptr[i] + bs[i >> 12];
        g_rowptr[i] = r;
        g_next[i]   = r;
    }
    if (i == 0) g_rowptr[NN] = NE;
}

// ---------------- CSR fill --------------------------------------------------------
__global__ void k_fill(const int* __restrict__ ei32){
    int e = blockIdx.x*blockDim.x + threadIdx.x;
    if (e >= NE) return;
    int s, d;
    if (g_is64){
        s = ei32[2*(size_t)e];
        d = ei32[2*((size_t)NE + e)];
    } else {
        s = ei32[e];
        d = ei32[NE + e];
    }
    s = clampi(s); d = clampi(d);
    int pos = atomicAdd(&g_next[d], 1);
    if (pos >= 0 && pos < NE) g_csr[pos] = s;
}

// ---------------- fused preprocess MLP + xw0 --------------------------------------
// 4 independent 128-thread groups per block, 8 nodes (4 pairs) per group-iteration.
// Named barriers per group; x software-pipelined via register prefetch.
// smem layout (floats):
#define P_W1  0         // 32768: blocked w1v[j*256+r] = W1[r][4j..4j+3]
#define P_W2  32768     // 4352 = 256*17 padded transpose
#define P_B2  37120     // 16
#define P_W0  37136     // 256 transposed: W0t[i*16+o] = W0[o][i]
#define P_XG  37392     // 4096: 4 groups x (4 pairs x 128 k x float2)
#define P_H1G 41488     // 8192: 4 groups x (4 pairs x 256 o x float2)
#define P_RG  49680     // 4096: 4 groups x (4 pairs x 8 part x 16 o x float2)
#define P_HSG 53776     // 512:  4 groups x (4 pairs x 16 o x float2)
#define PRE_SMEM_FLOATS 54288
#define PRE_SMEM_BYTES  (PRE_SMEM_FLOATS*4)   // 217152

#define GBAR() asm volatile("bar.sync %0, %1;" :: "r"(1 + wg), "r"(128) : "memory")

__global__ void __launch_bounds__(512, 1)
k_pre(const float* __restrict__ x,
      const float* __restrict__ p1W, const float* __restrict__ p1b,
      const float* __restrict__ p2W, const float* __restrict__ p2b){
    extern __shared__ float sm[];
    int t  = threadIdx.x;
    int wg = t >> 7;        // group 0..3
    int wt = t & 127;       // thread within group

    // stage weights once (all 512 threads)
    {
        float4* w1v = (float4*)(sm + P_W1);
        const float4* p1W4 = (const float4*)p1W;
        for (int i = t; i < 8192; i += 512){
            int j = i >> 8, r = i & 255;
            w1v[i] = p1W4[r*32 + j];
        }
        for (int i = t; i < 4096; i += 512){
            int k = i >> 4, o = i & 15;
            sm[P_W2 + k*17 + o] = p2W[o*256 + k];
        }
        if (t < 16) sm[P_B2 + t] = p2b[t];
        if (t < 256) sm[P_W0 + t] = g_W[(t & 15)*16 + (t >> 4)];
    }

    const int first  = (blockIdx.x*4 + wg)*8;
    const int stride = gridDim.x*32;

    float*  Xg  = sm + P_XG + wg*1024;
    float2* Xw  = (float2*)Xg;
    const ulonglong2* xq = (const ulonglong2*)Xg;
    float2* hbp = (float2*)(sm + P_H1G + wg*2048);
    const unsigned long long* hbu = (const unsigned long long*)(sm + P_H1G + wg*2048);
    unsigned long long* sru = (unsigned long long*)(sm + P_RG + wg*1024);
    const float2* srp = (const float2*)(sm + P_RG + wg*1024);
    float2* HSw = (float2*)(sm + P_HSG + wg*128);
    const unsigned long long* HSu = (const unsigned long long*)(sm + P_HSG + wg*128);

    // initial X fill for first batch
#pragma unroll
    for (int r = 0; r < 4; r++){
        int e = wt + 128*r, p = e >> 7, k = e & 127;
        Xw[p*128 + k] = make_float2(x[(size_t)(first + 2*p    )*128 + k],
                                    x[(size_t)(first + 2*p + 1)*128 + k]);
    }
    __syncthreads();   // weights + initial X visible

    float b0 = p1b[wt], b1 = p1b[128 + wt];

    for (int base = first; base < NN; base += stride){
        int nbase = base + stride;
        bool hasnext = (nbase < NN);

        // prefetch next batch's x into registers (overlaps with compute below)
        float2 nx0, nx1, nx2, nx3;
        if (hasnext){
            nx0 = make_float2(x[(size_t)(nbase    )*128 + wt], x[(size_t)(nbase + 1)*128 + wt]);
            nx1 = make_float2(x[(size_t)(nbase + 2)*128 + wt], x[(size_t)(nbase + 3)*128 + wt]);
            nx2 = make_float2(x[(size_t)(nbase + 4)*128 + wt], x[(size_t)(nbase + 5)*128 + wt]);
            nx3 = make_float2(x[(size_t)(nbase + 6)*128 + wt], x[(size_t)(nbase + 7)*128 + wt]);
        }

        // ---- layer 1: 2 outputs x 4 pairs per thread ----
        unsigned long long a00, a01, a02, a03, a10, a11, a12, a13;
        a00 = a01 = a02 = a03 = pk2(b0, b0);
        a10 = a11 = a12 = a13 = pk2(b1, b1);
        const float4* wv = (const float4*)(sm + P_W1);
#pragma unroll 2
        for (int j = 0; j < 32; j++){
            float4 wA = wv[j*256 + wt];
            float4 wB = wv[j*256 + 128 + wt];
            ulonglong2 x0a = xq[0*64 + 2*j], x0b = xq[0*64 + 2*j + 1];
            ulonglong2 x1a = xq[1*64 + 2*j], x1b = xq[1*64 + 2*j + 1];
            ulonglong2 x2a = xq[2*64 + 2*j], x2b = xq[2*64 + 2*j + 1];
            ulonglong2 x3a = xq[3*64 + 2*j], x3b = xq[3*64 + 2*j + 1];
            unsigned long long wA0 = pk2(wA.x, wA.x), wA1 = pk2(wA.y, wA.y);
            unsigned long long wA2 = pk2(wA.z, wA.z), wA3 = pk2(wA.w, wA.w);
            a00 = fma2(wA0, x0a.x, a00); a00 = fma2(wA1, x0a.y, a00);
            a00 = fma2(wA2, x0b.x, a00); a00 = fma2(wA3, x0b.y, a00);
            a01 = fma2(wA0, x1a.x, a01); a01 = fma2(wA1, x1a.y, a01);
            a01 = fma2(wA2, x1b.x, a01); a01 = fma2(wA3, x1b.y, a01);
            a02 = fma2(wA0, x2a.x, a02); a02 = fma2(wA1, x2a.y, a02);
            a02 = fma2(wA2, x2b.x, a02); a02 = fma2(wA3, x2b.y, a02);
            a03 = fma2(wA0, x3a.x, a03); a03 = fma2(wA1, x3a.y, a03);
            a03 = fma2(wA2, x3b.x, a03); a03 = fma2(wA3, x3b.y, a03);
            unsigned long long wB0 = pk2(wB.x, wB.x), wB1 = pk2(wB.y, wB.y);
            unsigned long long wB2 = pk2(wB.z, wB.z), wB3 = pk2(wB.w, wB.w);
            a10 = fma2(wB0, x0a.x, a10); a10 = fma2(wB1, x0a.y, a10);
            a10 = fma2(wB2, x0b.x, a10); a10 = fma2(wB3, x0b.y, a10);
            a11 = fma2(wB0, x1a.x, a11); a11 = fma2(wB1, x1a.y, a11);
            a11 = fma2(wB2, x1b.x, a11); a11 = fma2(wB3, x1b.y, a11);
            a12 = fma2(wB0, x2a.x, a12); a12 = fma2(wB1, x2a.y, a12);
            a12 = fma2(wB2, x2b.x, a12); a12 = fma2(wB3, x2b.y, a12);
            a13 = fma2(wB0, x3a.x, a13); a13 = fma2(wB1, x3a.y, a13);
            a13 = fma2(wB2, x3b.x, a13); a13 = fma2(wB3, x3b.y, a13);
        }
        {
            float2 y;
            y = upk2(a00); hbp[0*256 + wt]       = make_float2(lrelu(y.x), lrelu(y.y));
            y = upk2(a01); hbp[1*256 + wt]       = make_float2(lrelu(y.x), lrelu(y.y));
            y = upk2(a02); hbp[2*256 + wt]       = make_float2(lrelu(y.x), lrelu(y.y));
            y = upk2(a03); hbp[3*256 + wt]       = make_float2(lrelu(y.x), lrelu(y.y));
            y = upk2(a10); hbp[0*256 + 128 + wt] = make_float2(lrelu(y.x), lrelu(y.y));
            y = upk2(a11); hbp[1*256 + 128 + wt] = make_float2(lrelu(y.x), lrelu(y.y));
            y = upk2(a12); hbp[2*256 + 128 + wt] = make_float2(lrelu(y.x), lrelu(y.y));
            y = upk2(a13); hbp[3*256 + 128 + wt] = make_float2(lrelu(y.x), lrelu(y.y));
        }
        GBAR();   // h1 visible; X fully consumed

        // ---- store prefetched x (X is free now) + layer 2 partials ----
        if (hasnext){
            Xw[0*128 + wt] = nx0;
            Xw[1*128 + wt] = nx1;
            Xw[2*128 + wt] = nx2;
            Xw[3*128 + wt] = nx3;
        }
        {
            int o = wt & 15, part = wt >> 4;   // part 0..7, 32 k each
            unsigned long long c0 = 0ULL, c1 = 0ULL, c2 = 0ULL, c3 = 0ULL;
#pragma unroll
            for (int kk = 0; kk < 32; kk++){
                int k = part*32 + kk;
                float w2s = sm[P_W2 + k*17 + o];
                unsigned long long w2 = pk2(w2s, w2s);
                c0 = fma2(w2, hbu[0*256 + k], c0);
                c1 = fma2(w2, hbu[1*256 + k], c1);
                c2 = fma2(w2, hbu[2*256 + k], c2);
                c3 = fma2(w2, hbu[3*256 + k], c3);
            }
            sru[0*128 + part*16 + o] = c0;
            sru[1*128 + part*16 + o] = c1;
            sru[2*128 + part*16 + o] = c2;
            sru[3*128 + part*16 + o] = c3;
        }
        GBAR();   // partials visible

        // ---- final h (pair-packed) ----
        if (wt < 64){
            int p = wt >> 4, o = wt & 15;
            float sx = 0.f, sy = 0.f;
#pragma unroll
            for (int q = 0; q < 8; q++){
                float2 v = srp[p*128 + q*16 + o];
                sx += v.x; sy += v.y;
            }
            float bb2 = sm[P_B2 + o];
            HSw[p*16 + o] = make_float2(lrelu(sx + bb2), lrelu(sy + bb2));
        }
        GBAR();

        // ---- fused xw0 = (h @ W0^T) * dinv ----
        if (wt < 64){
            int p = wt >> 4, o = wt & 15;
            unsigned long long acc = 0ULL;
#pragma unroll
            for (int i = 0; i < 16; i++){
                float w = sm[P_W0 + i*16 + o];
                acc = fma2(pk2(w, w), HSu[p*16 + i], acc);
            }
            float2 v = upk2(acc);
            int n0 = base + 2*p, n1 = n0 + 1;
            g_xw[(size_t)n0*16 + o] = v.x * g_dinv[n0];
            g_xw[(size_t)n1*16 + o] = v.y * g_dinv[n1];
        }
        GBAR();   // HS/R free; X stable for next iteration
    }
}

// ---------------- gather layer 0 + fused xw1 ---------------------------------------
__global__ void __launch_bounds__(256)
k_gather0(const float* __restrict__ gcnb){
    __shared__ float Ws[256];   // W1 transposed: Ws[i*16+o] = W1[o][i]
    Ws[threadIdx.x] = g_W[256 + (threadIdx.x & 15)*16 + (threadIdx.x >> 4)];
    __syncthreads();

    int warp = (blockIdx.x*blockDim.x + threadIdx.x) >> 5;
    int lane = threadIdx.x & 31;
    if (warp >= NN) return;
    int node = warp;
    int slot = lane >> 2;
    int cg   = lane & 3;
    int beg = g_rowptr[node], end = g_rowptr[node + 1];
    const float4* xw4 = (const float4*)g_xw;

    float4 acc;
    if (slot == 0) acc = xw4[(size_t)node*4 + cg];
    else           acc = make_float4(0.f, 0.f, 0.f, 0.f);

    for (int j = beg + slot; j < end; j += 8){
        int s = g_csr[j];
        float4 v = xw4[(size_t)s*4 + cg];
        acc.x += v.x; acc.y += v.y; acc.z += v.z; acc.w += v.w;
    }
#pragma unroll
    for (int off = 4; off < 32; off <<= 1){
        acc.x += __shfl_xor_sync(0xffffffff, acc.x, off);
        acc.y += __shfl_xor_sync(0xffffffff, acc.y, off);
        acc.z += __shfl_xor_sync(0xffffffff, acc.z, off);
        acc.w += __shfl_xor_sync(0xffffffff, acc.w, off);
    }
    float di = g_dinv[node];
    const float* bp = gcnb + cg*4;   // l = 0
    float4 r;
    r.x = lrelu(di*acc.x + bp[0]);
    r.y = lrelu(di*acc.y + bp[1]);
    r.z = lrelu(di*acc.z + bp[2]);
    r.w = lrelu(di*acc.w + bp[3]);

    float hv[16];
    int qb = lane & ~3;
#pragma unroll
    for (int c = 0; c < 4; c++){
        int src = qb + c;
        hv[c*4+0] = __shfl_sync(0xffffffff, r.x, src);
        hv[c*4+1] = __shfl_sync(0xffffffff, r.y, src);
        hv[c*4+2] = __shfl_sync(0xffffffff, r.z, src);
        hv[c*4+3] = __shfl_sync(0xffffffff, r.w, src);
    }
    if (lane < 16){
        float a = 0.f;
#pragma unroll
        for (int i = 0; i < 16; i++) a += hv[i]*Ws[i*16 + lane];
        g_h[(size_t)node*16 + lane] = a * di;
    }
}

// ---------------- gather layer 1 + fused post heads ---------------------------------
__global__ void __launch_bounds__(256)
k_gather2(const float* __restrict__ gcnb,
          const float* __restrict__ po1W, const float* __restrict__ po1b,
          const float* __restrict__ poaW, const float* __restrict__ poab,
          float* __restrict__ out, int out_size){
    int warp = (blockIdx.x*blockDim.x + threadIdx.x) >> 5;
    int lane = threadIdx.x & 31;
    if (warp >= NN) return;
    int node = warp;
    int slot = lane >> 2;
    int cg   = lane & 3;
    int beg = g_rowptr[node], end = g_rowptr[node + 1];
    const float4* xw4 = (const float4*)g_h;

    float4 acc;
    if (slot == 0) acc = xw4[(size_t)node*4 + cg];
    else           acc = make_float4(0.f, 0.f, 0.f, 0.f);

    for (int j = beg + slot; j < end; j += 8){
        int s = g_csr[j];
        float4 v = xw4[(size_t)s*4 + cg];
        acc.x += v.x; acc.y += v.y; acc.z += v.z; acc.w += v.w;
    }
#pragma unroll
    for (int off = 4; off < 32; off <<= 1){
        acc.x += __shfl_xor_sync(0xffffffff, acc.x, off);
        acc.y += __shfl_xor_sync(0xffffffff, acc.y, off);
        acc.z += __shfl_xor_sync(0xffffffff, acc.z, off);
        acc.w += __shfl_xor_sync(0xffffffff, acc.w, off);
    }
    if (lane < 4){
        float di = g_dinv[node];
        const float* bp = gcnb + 16 + cg*4;   // l = 1
        float4 r;
        r.x = lrelu(di*acc.x + bp[0]);
        r.y = lrelu(di*acc.y + bp[1]);
        r.z = lrelu(di*acc.z + bp[2]);
        r.w = lrelu(di*acc.w + bp[3]);
        if (out_size >= 18*NN)
            ((float4*)(out + 2*NN))[(size_t)node*4 + cg] = r;
        int c0 = cg*4;
        float sp = r.x*(po1W[c0+0] + po1W[16+c0+0])
                 + r.y*(po1W[c0+1] + po1W[16+c0+1])
                 + r.z*(po1W[c0+2] + po1W[16+c0+2])
                 + r.w*(po1W[c0+3] + po1W[16+c0+3]);
        float ap = r.x*poaW[c0+0] + r.y*poaW[c0+1]
                 + r.z*poaW[c0+2] + r.w*poaW[c0+3];
        unsigned qm = 0xFu << ((lane >> 2) << 2);
        sp += __shfl_xor_sync(qm, sp, 1); sp += __shfl_xor_sync(qm, sp, 2);
        ap += __shfl_xor_sync(qm, ap, 1); ap += __shfl_xor_sync(qm, ap, 2);
        if (cg == 0){
            out[node] = sp + po1b[0] + po1b[1];
            if (out_size >= 2*NN) out[NN + node] = ap + poab[0];
        }
    }
}

// ---------------- launch --------------------------------------------------------------
extern "C" void kernel_launch(void* const* d_in, const int* in_sizes, int n_in,
                              void* d_out, int out_size){
    const float* x    = (const float*)d_in[0];
    const int*   ei32 = (const int*)d_in[1];
    const float* p1W  = (const float*)d_in[2];
    const float* p1b  = (const float*)d_in[3];
    const float* p2W  = (const float*)d_in[4];
    const float* p2b  = (const float*)d_in[5];
    const float* bih  = (const float*)d_in[6];
    const float* bhh  = (const float*)d_in[7];
    const float* wtW  = (const float*)d_in[8];
    const float* wtb  = (const float*)d_in[9];
    const float* gcnb = (const float*)d_in[10];
    const float* po1W = (const float*)d_in[11];
    const float* po1b = (const float*)d_in[12];
    const float* poaW = (const float*)d_in[13];
    const float* poab = (const float*)d_in[14];
    float* out = (float*)d_out;

    cudaFuncSetAttribute(k_pre, cudaFuncAttributeMaxDynamicSharedMemorySize,
                         PRE_SMEM_BYTES);

    const int NB_N = (NN + 255)/256;
    const int NB_E = (NE + 255)/256;
    const int NB_E2 = (NE/2 + 255)/256;
    const int NB_SCAN = (NN + 4095)/4096;   // 25
    const int NB_G = (NN*32 + 255)/256;     // warp per node
    const int NB_I = 2 + (NN + 511)/512;

    // launch index:        0       1        2        3 (profiled slot)
    k_init   <<<NB_I, 512>>>(ei32, bih, bhh, wtW, wtb);
    k_edges  <<<NB_E2, 256>>>(ei32);
    k_scan1  <<<NB_SCAN, 512>>>();
    k_pre    <<<148, 512, PRE_SMEM_BYTES>>>(x, p1W, p1b, p2W, p2b);
    k_scan3  <<<NB_N, 256>>>();
    k_fill   <<<NB_E, 256>>>(ei32);
    k_gather0<<<NB_G, 256>>>(gcnb);
    k_gather2<<<NB_G, 256>>>(gcnb, po1W, po1b, poaW, poab, out, out_size);
}

// round 11
// speedup vs baseline: 1.0835x; 1.0221x over previous
#include <cuda_runtime.h>
#include <math.h>

#define NN 100000
#define NE 3200000
#define SLOPE 0.01f

// ---------------- scratch (device globals; no allocation allowed) ----------
__device__ __align__(16) int   g_cnt   [NN];
__device__ __align__(16) int   g_rowptr[NN + 1];
__device__ __align__(16) int   g_next  [NN];
__device__ __align__(16) int   g_bsum  [32];
__device__ __align__(16) int   g_csr   [NE];
__device__ __align__(16) float g_dinv  [NN];
__device__ __align__(16) float g_h     [NN*16];   // xw1 after gather0
__device__ __align__(16) float g_xw    [NN*16];   // UNSCALED xw0 after k_pre
__device__ float g_W[2*256];
__device__ int   g_is64;

__device__ __forceinline__ float lrelu(float v){ return v > 0.f ? v : SLOPE*v; }
__device__ __forceinline__ int   clampi(int v){ return v < 0 ? 0 : (v >= NN ? NN-1 : v); }

// packed fp32x2 helpers (Blackwell)
__device__ __forceinline__ unsigned long long pk2(float a, float b){
    unsigned long long r;
    asm("mov.b64 %0, {%1, %2};" : "=l"(r) : "f"(a), "f"(b));
    return r;
}
__device__ __forceinline__ unsigned long long fma2(unsigned long long a,
                                                   unsigned long long b,
                                                   unsigned long long c){
    unsigned long long d;
    asm("fma.rn.f32x2 %0, %1, %2, %3;" : "=l"(d) : "l"(a), "l"(b), "l"(c));
    return d;
}
__device__ __forceinline__ float2 upk2(unsigned long long v){
    float2 r;
    asm("mov.b64 {%0, %1}, %2;" : "=f"(r.x), "=f"(r.y) : "l"(v));
    return r;
}

// ---------------- fused init: block0=dtype detect, block1=hyper, rest=cnt0 ----
__global__ void __launch_bounds__(512)
k_init(const int* __restrict__ ei32,
       const float* __restrict__ bih, const float* __restrict__ bhh,
       const float* __restrict__ wtW, const float* __restrict__ wtb){
    int b = blockIdx.x;
    if (b == 0){
        __shared__ int any;
        if (threadIdx.x == 0) any = 0;
        __syncthreads();
        int v = 0;
#pragma unroll
        for (int q = 0; q < 6; q++){
            int e = threadIdx.x + 512*q;
            v |= ei32[2*e + 1];
        }
        if (v) atomicOr(&any, 1);
        __syncthreads();
        if (threadIdx.x == 0) g_is64 = (any == 0) ? 1 : 0;
    } else if (b == 1){
        int t = threadIdx.x;
        int l = t >> 8, j = t & 255;
        float mem[16];
#pragma unroll
        for (int m = 0; m < 16; m++){
            float r = 1.f/(1.f + expf(-(bih[l*48 + m]      + bhh[l*48 + m])));
            float z = 1.f/(1.f + expf(-(bih[l*48 + 16 + m] + bhh[l*48 + 16 + m])));
            float n = tanhf(bih[l*48 + 32 + m] + r*bhh[l*48 + 32 + m]);
            mem[m] = (1.f - z) * n;
        }
        float acc = wtb[l*256 + j];
#pragma unroll
        for (int m = 0; m < 16; m++) acc += wtW[(l*256 + j)*16 + m] * mem[m];
        g_W[l*256 + j] = acc;
    } else {
        int i = (b - 2)*512 + threadIdx.x;
        if (i < NN) g_cnt[i] = 0;
    }
}

// ---------------- degree count (dst row only) ----------------------------------
__global__ void k_edges(const int* __restrict__ ei32){
    int p = blockIdx.x*blockDim.x + threadIdx.x;
    if (p >= NE/2) return;
    int d0, d1;
    if (g_is64){
        const longlong2* v = (const longlong2*)ei32;
        longlong2 dv = v[(NE >> 1) + p];
        d0 = (int)dv.x; d1 = (int)dv.y;
    } else {
        const int2* v = (const int2*)ei32;
        int2 dv = v[(NE >> 1) + p];
        d0 = dv.x; d1 = dv.y;
    }
    atomicAdd(&g_cnt[clampi(d0)], 1);
    atomicAdd(&g_cnt[clampi(d1)], 1);
}

// ---------------- exclusive scan over g_cnt -> g_rowptr (+ dinv fused) -----------
__global__ void k_scan1(){
    __shared__ int ts[512];
    int b = blockIdx.x, t = threadIdx.x;
    int base = b*4096 + t*8;
    int v[8]; int s = 0;
#pragma unroll
    for (int k = 0; k < 8; k++){
        v[k] = (base + k < NN) ? g_cnt[base + k] : 0;
        s += v[k];
        if (base + k < NN) g_dinv[base + k] = rsqrtf((float)v[k] + 1.0f);
    }
    ts[t] = s; __syncthreads();
#pragma unroll
    for (int off = 1; off < 512; off <<= 1){
        int y = (t >= off) ? ts[t - off] : 0;
        __syncthreads();
        ts[t] += y;
        __syncthreads();
    }
    if (t == 511) g_bsum[b] = ts[511];
    int run = ts[t] - s;
#pragma unroll
    for (int k = 0; k < 8; k++){
        if (base + k < NN) g_rowptr[base + k] = run;
        run += v[k];
    }
}
// scan3 with inline scan2
__global__ void k_scan3(){
    __shared__ int bs[32];
    if (threadIdx.x == 0){
        int run = 0;
        for (int j = 0; j < 25; j++){ bs[j] = run; run += g_bsum[j]; }
    }
    __syncthreads();
    int i = blockIdx.x*blockDim.x + threadIdx.x;
    if (i < NN){
        int r = g_rowptr[i] + bs[i >> 12];
        g_rowptr[i] = r;
        g_next[i]   = r;
    }
    if (i == 0) g_rowptr[NN] = NE;
}

// ---------------- CSR fill --------------------------------------------------------
__global__ void k_fill(const int* __restrict__ ei32){
    int e = blockIdx.x*blockDim.x + threadIdx.x;
    if (e >= NE) return;
    int s, d;
    if (g_is64){
        s = ei32[2*(size_t)e];
        d = ei32[2*((size_t)NE + e)];
    } else {
        s = ei32[e];
        d = ei32[NE + e];
    }
    s = clampi(s); d = clampi(d);
    int pos = atomicAdd(&g_next[d], 1);
    if (pos >= 0 && pos < NE) g_csr[pos] = s;
}

// ---------------- fused preprocess MLP + unscaled xw0 ------------------------------
// 4 independent 128-thread groups per block, 8 nodes (4 pairs) per group-iteration.
// NOTE: writes xw0u = h @ W0^T (NO dinv — dinv is produced concurrently on the
// CSR stream; gather0 folds dinv[s] per edge instead).
#define P_W1  0         // 32768: blocked w1v[j*256+r] = W1[r][4j..4j+3]
#define P_W2  32768     // 4352 = 256*17 padded transpose
#define P_B2  37120     // 16
#define P_W0  37136     // 256 transposed: W0t[i*16+o] = W0[o][i]
#define P_XG  37392     // 4096: 4 groups x (4 pairs x 128 k x float2)
#define P_H1G 41488     // 8192: 4 groups x (4 pairs x 256 o x float2)
#define P_RG  49680     // 4096: 4 groups x (4 pairs x 8 part x 16 o x float2)
#define P_HSG 53776     // 512:  4 groups x (4 pairs x 16 o x float2)
#define PRE_SMEM_FLOATS 54288
#define PRE_SMEM_BYTES  (PRE_SMEM_FLOATS*4)   // 217152

#define GBAR() asm volatile("bar.sync %0, %1;" :: "r"(1 + wg), "r"(128) : "memory")

__global__ void __launch_bounds__(512, 1)
k_pre(const float* __restrict__ x,
      const float* __restrict__ p1W, const float* __restrict__ p1b,
      const float* __restrict__ p2W, const float* __restrict__ p2b){
    extern __shared__ float sm[];
    int t  = threadIdx.x;
    int wg = t >> 7;
    int wt = t & 127;

    {
        float4* w1v = (float4*)(sm + P_W1);
        const float4* p1W4 = (const float4*)p1W;
        for (int i = t; i < 8192; i += 512){
            int j = i >> 8, r = i & 255;
            w1v[i] = p1W4[r*32 + j];
        }
        for (int i = t; i < 4096; i += 512){
            int k = i >> 4, o = i & 15;
            sm[P_W2 + k*17 + o] = p2W[o*256 + k];
        }
        if (t < 16) sm[P_B2 + t] = p2b[t];
        if (t < 256) sm[P_W0 + t] = g_W[(t & 15)*16 + (t >> 4)];
    }

    const int first  = (blockIdx.x*4 + wg)*8;
    const int stride = gridDim.x*32;

    float*  Xg  = sm + P_XG + wg*1024;
    float2* Xw  = (float2*)Xg;
    const ulonglong2* xq = (const ulonglong2*)Xg;
    float2* hbp = (float2*)(sm + P_H1G + wg*2048);
    const unsigned long long* hbu = (const unsigned long long*)(sm + P_H1G + wg*2048);
    unsigned long long* sru = (unsigned long long*)(sm + P_RG + wg*1024);
    const float2* srp = (const float2*)(sm + P_RG + wg*1024);
    float2* HSw = (float2*)(sm + P_HSG + wg*128);
    const unsigned long long* HSu = (const unsigned long long*)(sm + P_HSG + wg*128);

#pragma unroll
    for (int r = 0; r < 4; r++){
        int e = wt + 128*r, p = e >> 7, k = e & 127;
        Xw[p*128 + k] = make_float2(x[(size_t)(first + 2*p    )*128 + k],
                                    x[(size_t)(first + 2*p + 1)*128 + k]);
    }
    __syncthreads();

    float b0 = p1b[wt], b1 = p1b[128 + wt];

    for (int base = first; base < NN; base += stride){
        int nbase = base + stride;
        bool hasnext = (nbase < NN);

        float2 nx0, nx1, nx2, nx3;
        if (hasnext){
            nx0 = make_float2(x[(size_t)(nbase    )*128 + wt], x[(size_t)(nbase + 1)*128 + wt]);
            nx1 = make_float2(x[(size_t)(nbase + 2)*128 + wt], x[(size_t)(nbase + 3)*128 + wt]);
            nx2 = make_float2(x[(size_t)(nbase + 4)*128 + wt], x[(size_t)(nbase + 5)*128 + wt]);
            nx3 = make_float2(x[(size_t)(nbase + 6)*128 + wt], x[(size_t)(nbase + 7)*128 + wt]);
        }

        unsigned long long a00, a01, a02, a03, a10, a11, a12, a13;
        a00 = a01 = a02 = a03 = pk2(b0, b0);
        a10 = a11 = a12 = a13 = pk2(b1, b1);
        const float4* wv = (const float4*)(sm + P_W1);
#pragma unroll 2
        for (int j = 0; j < 32; j++){
            float4 wA = wv[j*256 + wt];
            float4 wB = wv[j*256 + 128 + wt];
            ulonglong2 x0a = xq[0*64 + 2*j], x0b = xq[0*64 + 2*j + 1];
            ulonglong2 x1a = xq[1*64 + 2*j], x1b = xq[1*64 + 2*j + 1];
            ulonglong2 x2a = xq[2*64 + 2*j], x2b = xq[2*64 + 2*j + 1];
            ulonglong2 x3a = xq[3*64 + 2*j], x3b = xq[3*64 + 2*j + 1];
            unsigned long long wA0 = pk2(wA.x, wA.x), wA1 = pk2(wA.y, wA.y);
            unsigned long long wA2 = pk2(wA.z, wA.z), wA3 = pk2(wA.w, wA.w);
            a00 = fma2(wA0, x0a.x, a00); a00 = fma2(wA1, x0a.y, a00);
            a00 = fma2(wA2, x0b.x, a00); a00 = fma2(wA3, x0b.y, a00);
            a01 = fma2(wA0, x1a.x, a01); a01 = fma2(wA1, x1a.y, a01);
            a01 = fma2(wA2, x1b.x, a01); a01 = fma2(wA3, x1b.y, a01);
            a02 = fma2(wA0, x2a.x, a02); a02 = fma2(wA1, x2a.y, a02);
            a02 = fma2(wA2, x2b.x, a02); a02 = fma2(wA3, x2b.y, a02);
            a03 = fma2(wA0, x3a.x, a03); a03 = fma2(wA1, x3a.y, a03);
            a03 = fma2(wA2, x3b.x, a03); a03 = fma2(wA3, x3b.y, a03);
            unsigned long long wB0 = pk2(wB.x, wB.x), wB1 = pk2(wB.y, wB.y);
            unsigned long long wB2 = pk2(wB.z, wB.z), wB3 = pk2(wB.w, wB.w);
            a10 = fma2(wB0, x0a.x, a10); a10 = fma2(wB1, x0a.y, a10);
            a10 = fma2(wB2, x0b.x, a10); a10 = fma2(wB3, x0b.y, a10);
            a11 = fma2(wB0, x1a.x, a11); a11 = fma2(wB1, x1a.y, a11);
            a11 = fma2(wB2, x1b.x, a11); a11 = fma2(wB3, x1b.y, a11);
            a12 = fma2(wB0, x2a.x, a12); a12 = fma2(wB1, x2a.y, a12);
            a12 = fma2(wB2, x2b.x, a12); a12 = fma2(wB3, x2b.y, a12);
            a13 = fma2(wB0, x3a.x, a13); a13 = fma2(wB1, x3a.y, a13);
            a13 = fma2(wB2, x3b.x, a13); a13 = fma2(wB3, x3b.y, a13);
        }
        {
            float2 y;
            y = upk2(a00); hbp[0*256 + wt]       = make_float2(lrelu(y.x), lrelu(y.y));
            y = upk2(a01); hbp[1*256 + wt]       = make_float2(lrelu(y.x), lrelu(y.y));
            y = upk2(a02); hbp[2*256 + wt]       = make_float2(lrelu(y.x), lrelu(y.y));
            y = upk2(a03); hbp[3*256 + wt]       = make_float2(lrelu(y.x), lrelu(y.y));
            y = upk2(a10); hbp[0*256 + 128 + wt] = make_float2(lrelu(y.x), lrelu(y.y));
            y = upk2(a11); hbp[1*256 + 128 + wt] = make_float2(lrelu(y.x), lrelu(y.y));
            y = upk2(a12); hbp[2*256 + 128 + wt] = make_float2(lrelu(y.x), lrelu(y.y));
            y = upk2(a13); hbp[3*256 + 128 + wt] = make_float2(lrelu(y.x), lrelu(y.y));
        }
        GBAR();

        if (hasnext){
            Xw[0*128 + wt] = nx0;
            Xw[1*128 + wt] = nx1;
            Xw[2*128 + wt] = nx2;
            Xw[3*128 + wt] = nx3;
        }
        {
            int o = wt & 15, part = wt >> 4;
            unsigned long long c0 = 0ULL, c1 = 0ULL, c2 = 0ULL, c3 = 0ULL;
#pragma unroll
            for (int kk = 0; kk < 32; kk++){
                int k = part*32 + kk;
                float w2s = sm[P_W2 + k*17 + o];
                unsigned long long w2 = pk2(w2s, w2s);
                c0 = fma2(w2, hbu[0*256 + k], c0);
                c1 = fma2(w2, hbu[1*256 + k], c1);
                c2 = fma2(w2, hbu[2*256 + k], c2);
                c3 = fma2(w2, hbu[3*256 + k], c3);
            }
            sru[0*128 + part*16 + o] = c0;
            sru[1*128 + part*16 + o] = c1;
            sru[2*128 + part*16 + o] = c2;
            sru[3*128 + part*16 + o] = c3;
        }
        GBAR();

        if (wt < 64){
            int p = wt >> 4, o = wt & 15;
            float sx = 0.f, sy = 0.f;
#pragma unroll
            for (int q = 0; q < 8; q++){
                float2 v = srp[p*128 + q*16 + o];
                sx += v.x; sy += v.y;
            }
            float bb2 = sm[P_B2 + o];
            HSw[p*16 + o] = make_float2(lrelu(sx + bb2), lrelu(sy + bb2));
        }
        GBAR();

        // unscaled xw0 = h @ W0^T
        if (wt < 64){
            int p = wt >> 4, o = wt & 15;
            unsigned long long acc = 0ULL;
#pragma unroll
            for (int i = 0; i < 16; i++){
                float w = sm[P_W0 + i*16 + o];
                acc = fma2(pk2(w, w), HSu[p*16 + i], acc);
            }
            float2 v = upk2(acc);
            int n0 = base + 2*p;
            g_xw[(size_t)n0*16 + o]       = v.x;
            g_xw[(size_t)(n0 + 1)*16 + o] = v.y;
        }
        GBAR();
    }
}

// ---------------- gather layer 0 (dinv folded per edge) + fused xw1 -----------------
__global__ void __launch_bounds__(256)
k_gather0(const float* __restrict__ gcnb){
    __shared__ float Ws[256];   // W1 transposed
    Ws[threadIdx.x] = g_W[256 + (threadIdx.x & 15)*16 + (threadIdx.x >> 4)];
    __syncthreads();

    int warp = (blockIdx.x*blockDim.x + threadIdx.x) >> 5;
    int lane = threadIdx.x & 31;
    if (warp >= NN) return;
    int node = warp;
    int slot = lane >> 2;
    int cg   = lane & 3;
    int beg = g_rowptr[node], end = g_rowptr[node + 1];
    const float4* xw4 = (const float4*)g_xw;
    float di = g_dinv[node];

    float4 acc;
    if (slot == 0){
        float4 v = xw4[(size_t)node*4 + cg];   // self loop: dinv[d]*xw0u[d]
        acc = make_float4(v.x*di, v.y*di, v.z*di, v.w*di);
    } else {
        acc = make_float4(0.f, 0.f, 0.f, 0.f);
    }

    for (int j = beg + slot; j < end; j += 8){
        int s = g_csr[j];
        float ds = g_dinv[s];
        float4 v = xw4[(size_t)s*4 + cg];
        acc.x = fmaf(v.x, ds, acc.x);
        acc.y = fmaf(v.y, ds, acc.y);
        acc.z = fmaf(v.z, ds, acc.z);
        acc.w = fmaf(v.w, ds, acc.w);
    }
#pragma unroll
    for (int off = 4; off < 32; off <<= 1){
        acc.x += __shfl_xor_sync(0xffffffff, acc.x, off);
        acc.y += __shfl_xor_sync(0xffffffff, acc.y, off);
        acc.z += __shfl_xor_sync(0xffffffff, acc.z, off);
        acc.w += __shfl_xor_sync(0xffffffff, acc.w, off);
    }
    const float* bp = gcnb + cg*4;   // l = 0
    float4 r;
    r.x = lrelu(di*acc.x + bp[0]);
    r.y = lrelu(di*acc.y + bp[1]);
    r.z = lrelu(di*acc.z + bp[2]);
    r.w = lrelu(di*acc.w + bp[3]);

    float hv[16];
    int qb = lane & ~3;
#pragma unroll
    for (int c = 0; c < 4; c++){
        int src = qb + c;
        hv[c*4+0] = __shfl_sync(0xffffffff, r.x, src);
        hv[c*4+1] = __shfl_sync(0xffffffff, r.y, src);
        hv[c*4+2] = __shfl_sync(0xffffffff, r.z, src);
        hv[c*4+3] = __shfl_sync(0xffffffff, r.w, src);
    }
    if (lane < 16){
        float a = 0.f;
#pragma unroll
        for (int i = 0; i < 16; i++) a += hv[i]*Ws[i*16 + lane];
        g_h[(size_t)node*16 + lane] = a * di;   // xw1 (scaled)
    }
}

// ---------------- gather layer 1 + fused post heads ---------------------------------
__global__ void __launch_bounds__(256)
k_gather2(const float* __restrict__ gcnb,
          const float* __restrict__ po1W, const float* __restrict__ po1b,
          const float* __restrict__ poaW, const float* __restrict__ poab,
          float* __restrict__ out, int out_size){
    int warp = (blockIdx.x*blockDim.x + threadIdx.x) >> 5;
    int lane = threadIdx.x & 31;
    if (warp >= NN) return;
    int node = warp;
    int slot = lane >> 2;
    int cg   = lane & 3;
    int beg = g_rowptr[node], end = g_rowptr[node + 1];
    const float4* xw4 = (const float4*)g_h;

    float4 acc;
    if (slot == 0) acc = xw4[(size_t)node*4 + cg];
    else           acc = make_float4(0.f, 0.f, 0.f, 0.f);

    for (int j = beg + slot; j < end; j += 8){
        int s = g_csr[j];
        float4 v = xw4[(size_t)s*4 + cg];
        acc.x += v.x; acc.y += v.y; acc.z += v.z; acc.w += v.w;
    }
#pragma unroll
    for (int off = 4; off < 32; off <<= 1){
        acc.x += __shfl_xor_sync(0xffffffff, acc.x, off);
        acc.y += __shfl_xor_sync(0xffffffff, acc.y, off);
        acc.z += __shfl_xor_sync(0xffffffff, acc.z, off);
        acc.w += __shfl_xor_sync(0xffffffff, acc.w, off);
    }
    if (lane < 4){
        float di = g_dinv[node];
        const float* bp = gcnb + 16 + cg*4;
        float4 r;
        r.x = lrelu(di*acc.x + bp[0]);
        r.y = lrelu(di*acc.y + bp[1]);
        r.z = lrelu(di*acc.z + bp[2]);
        r.w = lrelu(di*acc.w + bp[3]);
        if (out_size >= 18*NN)
            ((float4*)(out + 2*NN))[(size_t)node*4 + cg] = r;
        int c0 = cg*4;
        float sp = r.x*(po1W[c0+0] + po1W[16+c0+0])
                 + r.y*(po1W[c0+1] + po1W[16+c0+1])
                 + r.z*(po1W[c0+2] + po1W[16+c0+2])
                 + r.w*(po1W[c0+3] + po1W[16+c0+3]);
        float ap = r.x*poaW[c0+0] + r.y*poaW[c0+1]
                 + r.z*poaW[c0+2] + r.w*poaW[c0+3];
        unsigned qm = 0xFu << ((lane >> 2) << 2);
        sp += __shfl_xor_sync(qm, sp, 1); sp += __shfl_xor_sync(qm, sp, 2);
        ap += __shfl_xor_sync(qm, ap, 1); ap += __shfl_xor_sync(qm, ap, 2);
        if (cg == 0){
            out[node] = sp + po1b[0] + po1b[1];
            if (out_size >= 2*NN) out[NN + node] = ap + poab[0];
        }
    }
}

// ---------------- launch --------------------------------------------------------------
extern "C" void kernel_launch(void* const* d_in, const int* in_sizes, int n_in,
                              void* d_out, int out_size){
    const float* x    = (const float*)d_in[0];
    const int*   ei32 = (const int*)d_in[1];
    const float* p1W  = (const float*)d_in[2];
    const float* p1b  = (const float*)d_in[3];
    const float* p2W  = (const float*)d_in[4];
    const float* p2b  = (const float*)d_in[5];
    const float* bih  = (const float*)d_in[6];
    const float* bhh  = (const float*)d_in[7];
    const float* wtW  = (const float*)d_in[8];
    const float* wtb  = (const float*)d_in[9];
    const float* gcnb = (const float*)d_in[10];
    const float* po1W = (const float*)d_in[11];
    const float* po1b = (const float*)d_in[12];
    const float* poaW = (const float*)d_in[13];
    const float* poab = (const float*)d_in[14];
    float* out = (float*)d_out;

    cudaFuncSetAttribute(k_pre, cudaFuncAttributeMaxDynamicSharedMemorySize,
                         PRE_SMEM_BYTES);

    const int NB_N = (NN + 255)/256;
    const int NB_E = (NE + 255)/256;
    const int NB_E2 = (NE/2 + 255)/256;
    const int NB_SCAN = (NN + 4095)/4096;   // 25
    const int NB_G = (NN*32 + 255)/256;     // warp per node
    const int NB_I = 2 + (NN + 511)/512;

    // capture-graph fork: CSR build (stream s2) runs concurrently with k_pre (stream 0)
    cudaStream_t s2 = 0;
    cudaEvent_t  evA = 0, evB = 0;
    bool fork = (cudaStreamCreateWithFlags(&s2, cudaStreamNonBlocking) == cudaSuccess);
    if (fork) fork = (cudaEventCreateWithFlags(&evA, cudaEventDisableTiming) == cudaSuccess);
    if (fork) fork = (cudaEventCreateWithFlags(&evB, cudaEventDisableTiming) == cudaSuccess);
    // NOTE: streams/events are intentionally NOT destroyed here — destroying a
    // forked stream before EndCapture invalidates the capture. They are
    // host-side objects; kernel_launch is invoked only a handful of times.

    k_init<<<NB_I, 512>>>(ei32, bih, bhh, wtW, wtb);

    if (fork){
        cudaEventRecord(evA, 0);
        cudaStreamWaitEvent(s2, evA, 0);
        k_edges<<<NB_E2, 256, 0, s2>>>(ei32);
        k_scan1<<<NB_SCAN, 512, 0, s2>>>();
        k_scan3<<<NB_N, 256, 0, s2>>>();
        k_fill <<<NB_E, 256, 0, s2>>>(ei32);
        cudaEventRecord(evB, s2);
        k_pre  <<<148, 512, PRE_SMEM_BYTES>>>(x, p1W, p1b, p2W, p2b);  // concurrent
        cudaStreamWaitEvent(0, evB, 0);
    } else {
        k_edges<<<NB_E2, 256>>>(ei32);
        k_scan1<<<NB_SCAN, 512>>>();
        k_scan3<<<NB_N, 256>>>();
        k_fill <<<NB_E, 256>>>(ei32);
        k_pre  <<<148, 512, PRE_SMEM_BYTES>>>(x, p1W, p1b, p2W, p2b);
    }

    k_gather0<<<NB_G, 256>>>(gcnb);
    k_gather2<<<NB_G, 256>>>(gcnb, po1W, po1b, poaW, poab, out, out_size);
}